// round 8
// baseline (speedup 1.0000x reference)
#include <cuda_runtime.h>
#include <cuda_fp16.h>
#include <mma.h>
#include <cstddef>
#include <cstdint>

using namespace nvcuda;

#define V    6912
#define G4   27648   // 4*V
#define BSZ  16
#define TT   8
#define TR   4

// ---------------- device scratch (no allocation allowed) ----------------
// Gate-interleaved layouts: column/row index n' = j*4 + g  (g: 0=i,1=f,2=g,3=o)
__device__ __half g_whh16[(size_t)G4 * V];   // fp16 W_hh_enc, rows interleaved
__device__ __half g_x16 [128 * V];           // x fp16
__device__ __half g_h16 [2][BSZ * V];        // encoder h fp16, PING-PONG buffers
__device__ __half g_hd16[BSZ * TR * V];      // decoder h_d (fp16, GEMM A)
__device__ float  g_h   [BSZ * V];           // encoder h fp32 (fc_enc)
__device__ float  g_c   [BSZ * V];
__device__ float  g_xg  [128 * G4];          // xg, cols interleaved (atomic target)
__device__ float  g_dec [BSZ * TR * V];      // fc_dec accumulator (atomic)
__device__ float  g_bep [G4];                // b_enc permuted to interleave
__device__ float  g_bdp [G4];                // b_dec permuted
__device__ float  g_widp[G4];                // W_ih_dec permuted

__device__ __forceinline__ float sigf(float x) { return 1.0f / (1.0f + expf(-x)); }

__device__ __forceinline__ uint4 pack8(float4 a, float4 b)
{
    __half2 h0 = __floats2half2_rn(a.x, a.y);
    __half2 h1 = __floats2half2_rn(a.z, a.w);
    __half2 h2 = __floats2half2_rn(b.x, b.y);
    __half2 h3 = __floats2half2_rn(b.z, b.w);
    uint4 u;
    u.x = *reinterpret_cast<unsigned*>(&h0);
    u.y = *reinterpret_cast<unsigned*>(&h1);
    u.z = *reinterpret_cast<unsigned*>(&h2);
    u.w = *reinterpret_cast<unsigned*>(&h3);
    return u;
}

// =====================================================================
__global__ void conv16_kernel(const float* __restrict__ src,
                              __half* __restrict__ dst, int n8)
{
    int idx = blockIdx.x * 256 + threadIdx.x;
    if (idx >= n8) return;
    const float4* s = (const float4*)src + (size_t)idx * 2;
    ((uint4*)dst)[idx] = pack8(s[0], s[1]);
}

__global__ void zero_kernel(float* __restrict__ dst, int n4)
{
    int idx = blockIdx.x * 256 + threadIdx.x;
    if (idx < n4) ((float4*)dst)[idx] = make_float4(0.f, 0.f, 0.f, 0.f);
}

// permute gate vectors: out[j*4+g] = in[g*V+j]
__global__ void prep_kernel(const float* __restrict__ be,
                            const float* __restrict__ bd,
                            const float* __restrict__ wid)
{
    int idx = blockIdx.x * 256 + threadIdx.x;
    if (idx >= G4) return;
    int src = (idx & 3) * V + (idx >> 2);
    g_bep[idx]  = be[src];
    g_bdp[idx]  = bd[src];
    g_widp[idx] = wid[src];
}

// =====================================================================
// Register-staged fp16-MMA GEMM, atomic-reduce epilogue (xg / fc_dec).
//   C[m0+m][n] += sum_{k slice} A[m0+m][k] * B_src[n][k]
//   PERM: B fp32 row n read from row (n&3)*V + (n>>2)  (gate interleave)
// =====================================================================
template<int BM, int BK, bool PERM>
__global__ __launch_bounds__(256)
void gemm16(const __half* __restrict__ A, const float* __restrict__ Bf,
            float* __restrict__ C, int N, int klen)
{
    constexpr int BNB = 128, LDS = BK + 8;
    __shared__ __align__(16) __half sA[2][BM][LDS];
    __shared__ __align__(16) __half sB[2][BNB][LDS];
    __shared__ __align__(16) float  sC[BM][BNB + 4];

    const int tid   = threadIdx.x;
    const int n0    = blockIdx.x * BNB;
    const int kbase = blockIdx.y * klen;
    const int m0    = blockIdx.z * BM;
    const int niter = klen / BK;

    constexpr int WARPS_M = (BM <= 16) ? 1 : 2;
    constexpr int WARPS_N = 8 / WARPS_M;
    constexpr int WM = BM / WARPS_M, WN = BNB / WARPS_N;
    constexpr int MF = WM / 16, NF = WN / 16;
    const int w  = tid >> 5;
    const int wm = w / WARPS_N, wn = w % WARPS_N;

    wmma::fragment<wmma::accumulator, 16, 16, 16, float> acc[MF][NF];
#pragma unroll
    for (int i = 0; i < MF; i++)
#pragma unroll
        for (int j = 0; j < NF; j++) wmma::fill_fragment(acc[i][j], 0.0f);

    constexpr int CPR   = BK / 8;
    constexpr int BCH   = BNB * CPR / 256;
    constexpr int ACH_T = BM * CPR;
    constexpr int ACH   = (ACH_T + 255) / 256;

    uint4 rb[BCH], ra[ACH];

    auto load = [&](int k0) {
#pragma unroll
        for (int p = 0; p < BCH; p++) {
            int c = tid + p * 256;
            int row = c / CPR, kc = (c % CPR) * 8;
            int nn = n0 + row;
            size_t srow = PERM ? ((size_t)(nn & 3) * V + (nn >> 2)) : (size_t)nn;
            const float* s = Bf + srow * V + k0 + kc;
            rb[p] = pack8(*(const float4*)s, *(const float4*)(s + 4));
        }
#pragma unroll
        for (int p = 0; p < ACH; p++) {
            int c = tid + p * 256;
            if (ACH_T >= (p + 1) * 256 || c < ACH_T) {
                int row = c / CPR, kc = (c % CPR) * 8;
                ra[p] = *(const uint4*)(A + (size_t)(m0 + row) * V + k0 + kc);
            }
        }
    };
    auto store = [&](int buf) {
#pragma unroll
        for (int p = 0; p < BCH; p++) {
            int c = tid + p * 256;
            int row = c / CPR, kc = (c % CPR) * 8;
            *(uint4*)(&sB[buf][row][kc]) = rb[p];
        }
#pragma unroll
        for (int p = 0; p < ACH; p++) {
            int c = tid + p * 256;
            if (ACH_T >= (p + 1) * 256 || c < ACH_T) {
                int row = c / CPR, kc = (c % CPR) * 8;
                *(uint4*)(&sA[buf][row][kc]) = ra[p];
            }
        }
    };

    load(kbase);
    store(0);
    if (niter > 1) load(kbase + BK);
    __syncthreads();

    for (int i = 0; i < niter; i++) {
        int p = i & 1;
        if (i + 1 < niter) store(p ^ 1);
        if (i + 2 < niter) load(kbase + (i + 2) * BK);
#pragma unroll
        for (int kk = 0; kk < BK; kk += 16) {
            wmma::fragment<wmma::matrix_a, 16, 16, 16, __half, wmma::row_major> af[MF];
            wmma::fragment<wmma::matrix_b, 16, 16, 16, __half, wmma::col_major> bf[NF];
#pragma unroll
            for (int i_ = 0; i_ < MF; i_++)
                wmma::load_matrix_sync(af[i_], &sA[p][wm * WM + i_ * 16][kk], LDS);
#pragma unroll
            for (int j_ = 0; j_ < NF; j_++)
                wmma::load_matrix_sync(bf[j_], &sB[p][wn * WN + j_ * 16][kk], LDS);
#pragma unroll
            for (int i_ = 0; i_ < MF; i_++)
#pragma unroll
                for (int j_ = 0; j_ < NF; j_++)
                    wmma::mma_sync(acc[i_][j_], af[i_], bf[j_], acc[i_][j_]);
        }
        __syncthreads();
    }

#pragma unroll
    for (int i_ = 0; i_ < MF; i_++)
#pragma unroll
        for (int j_ = 0; j_ < NF; j_++)
            wmma::store_matrix_sync(&sC[wm * WM + i_ * 16][wn * WN + j_ * 16],
                                    acc[i_][j_], BNB + 4, wmma::mem_row_major);
    __syncthreads();
    for (int c = tid; c < BM * BNB; c += 256) {
        int m = c / BNB, n = c - m * BNB;
        atomicAdd(&C[(size_t)(m0 + m) * N + n0 + n], sC[m][n]);
    }
}

// =====================================================================
// Fused LSTM-step epilogues (block owns 16 complete units j, all gates).
// hout: fp16 h buffer to write (ping-pong partner of the one being read).
// =====================================================================
__device__ __forceinline__ void enc_epilogue(float (*sF)[64], int jbase, int t,
                                             __half* __restrict__ hout)
{
    int tid = threadIdx.x;
    int b = tid >> 4, jl = tid & 15;
    int jg = jbase + jl;
    float4 pre = *(float4*)&sF[b][jl * 4];
    float4 xg4 = *(const float4*)&g_xg[(size_t)(b * 8 + t) * G4 + (size_t)jg * 4];
    float4 bb  = *(const float4*)&g_bep[jg * 4];
    float i_ = sigf (pre.x + xg4.x + bb.x);
    float f_ = sigf (pre.y + xg4.y + bb.y);
    float gg = tanhf(pre.z + xg4.z + bb.z);
    float o_ = sigf (pre.w + xg4.w + bb.w);
    int idx = b * V + jg;
    float c = f_ * g_c[idx] + i_ * gg;
    g_c[idx] = c;
    float h = o_ * tanhf(c);
    g_h[idx]  = h;
    hout[idx] = __float2half(h);
}

__device__ __forceinline__ void dec_epilogue(float (*sF)[64], int jbase,
                                             const float* __restrict__ xrev)
{
    int tid = threadIdx.x;
    int b = tid >> 4, jl = tid & 15;
    int jg = jbase + jl;
    float4 pre = *(float4*)&sF[b][jl * 4];
    float4 bb  = *(const float4*)&g_bdp[jg * 4];
    float4 ww  = *(const float4*)&g_widp[jg * 4];
    float bi = pre.x + bb.x, bf = pre.y + bb.y;
    float bg = pre.z + bb.z, bo = pre.w + bb.w;
    float ce = g_c[b * V + jg];
#pragma unroll
    for (int tr = 0; tr < TR; tr++) {
        float xr = xrev[b * TR + tr];
        float i_ = sigf (bi + xr * ww.x);
        float f_ = sigf (bf + xr * ww.y);
        float gg = tanhf(bg + xr * ww.z);
        float o_ = sigf (bo + xr * ww.w);
        float cd = f_ * ce + i_ * gg;
        size_t o = (size_t)(b * TR + tr) * V + jg;
        g_hd16[o] = __float2half(o_ * tanhf(cd));
        g_dec[o]  = 0.f;                 // pre-zero for fc_dec atomics
    }
}

// =====================================================================
// Fused recurrence step, fp16 interleaved weights (steps 2..7).
// Reads h from g_h16[(t+1)&1], writes h_t to g_h16[t&1]  (no race).
// Smem union: epilogue scratch aliases the staging buffers.
// =====================================================================
__global__ __launch_bounds__(256) void rec_ca_kernel(int t)
{
    constexpr int BK = 64, STAGES = 4, BNN = 64, LDS = BK + 8;
    union SM {
        struct { __half A[STAGES][16][LDS]; __half B[STAGES][BNN][LDS]; } st;
        struct { float R[4][16][68]; float F[16][64]; } ep;
    };
    __shared__ __align__(16) SM sm;

    const __half* hin  = g_h16[(t + 1) & 1];
    __half*       hout = g_h16[t & 1];

    const int tid = threadIdx.x;
    const int w   = tid >> 5;
    const int n0  = blockIdx.x * BNN;
    const int niter = V / BK;   // 108

    wmma::fragment<wmma::accumulator, 16, 16, 16, float> acc[4];
#pragma unroll
    for (int f = 0; f < 4; f++) wmma::fill_fragment(acc[f], 0.0f);

    auto stage = [&](int s, int k0) {
#pragma unroll
        for (int p = 0; p < 2; p++) {
            int c = tid + p * 256;
            int row = c >> 3, kc = (c & 7) * 8;
            uint32_t d = (uint32_t)__cvta_generic_to_shared(&sm.st.B[s][row][kc]);
            const void* g = g_whh16 + (size_t)(n0 + row) * V + k0 + kc;
            asm volatile("cp.async.cg.shared.global [%0], [%1], 16;\n" :: "r"(d), "l"(g));
        }
        if (tid < 128) {
            int row = tid >> 3, kc = (tid & 7) * 8;
            uint32_t d = (uint32_t)__cvta_generic_to_shared(&sm.st.A[s][row][kc]);
            const void* g = hin + (size_t)row * V + k0 + kc;
            asm volatile("cp.async.cg.shared.global [%0], [%1], 16;\n" :: "r"(d), "l"(g));
        }
        asm volatile("cp.async.commit_group;\n");
    };

    int issued = 0;
    for (; issued < STAGES - 1; issued++) stage(issued, issued * BK);

    for (int i = 0; i < niter; i++) {
        if (issued < niter) { stage(issued % STAGES, issued * BK); issued++; }
        else                { asm volatile("cp.async.commit_group;\n"); }
        asm volatile("cp.async.wait_group %0;\n" :: "n"(STAGES - 1));
        __syncthreads();
        int s = i % STAGES;
        if (w < 4 && (i & 3) == w) {
#pragma unroll
            for (int kk = 0; kk < BK; kk += 16) {
                wmma::fragment<wmma::matrix_a, 16, 16, 16, __half, wmma::row_major> af;
                wmma::load_matrix_sync(af, &sm.st.A[s][0][kk], LDS);
#pragma unroll
                for (int nf = 0; nf < 4; nf++) {
                    wmma::fragment<wmma::matrix_b, 16, 16, 16, __half, wmma::col_major> bf;
                    wmma::load_matrix_sync(bf, &sm.st.B[s][nf * 16][kk], LDS);
                    wmma::mma_sync(acc[nf], af, bf, acc[nf]);
                }
            }
        }
        __syncthreads();
    }

    // epilogue scratch aliases staging buffers — safe after the sync above
    if (w < 4)
#pragma unroll
        for (int nf = 0; nf < 4; nf++)
            wmma::store_matrix_sync(&sm.ep.R[w][0][nf * 16], acc[nf], 68,
                                    wmma::mem_row_major);
    __syncthreads();
    for (int c = tid; c < 16 * 64; c += 256) {
        int m = c >> 6, n = c & 63;
        sm.ep.F[m][n] = sm.ep.R[0][m][n] + sm.ep.R[1][m][n]
                      + sm.ep.R[2][m][n] + sm.ep.R[3][m][n];
    }
    __syncthreads();
    enc_epilogue(sm.ep.F, blockIdx.x * 16, t, hout);
}

// =====================================================================
// Fused recurrence/decoder step, fp32 weights read with gate-interleave
// row permutation + in-register fp16 convert.  WRITEB: persist fp16 copy.
// Enc: reads g_h16[(t+1)&1], writes g_h16[t&1].  Dec: pass t=0 (reads buf1).
// =====================================================================
template<bool WRITEB, bool DEC>
__global__ __launch_bounds__(256) void rec_f32_kernel(
    const float* __restrict__ W, int t, const float* __restrict__ xrev)
{
    constexpr int BK = 64, BNN = 64, LDS = BK + 8;
    union SM {
        struct { __half A[2][16][LDS]; __half B[2][BNN][LDS]; } st;
        struct { float R[4][16][68]; float F[16][64]; } ep;
    };
    __shared__ __align__(16) SM sm;

    const __half* hin  = g_h16[(t + 1) & 1];
    __half*       hout = g_h16[t & 1];

    const int tid = threadIdx.x;
    const int w   = tid >> 5;
    const int n0  = blockIdx.x * BNN;
    const int niter = V / BK;   // 108

    wmma::fragment<wmma::accumulator, 16, 16, 16, float> acc[4];
#pragma unroll
    for (int f = 0; f < 4; f++) wmma::fill_fragment(acc[f], 0.0f);

    uint4 rb[2], ra;

    auto load = [&](int k0) {
#pragma unroll
        for (int p = 0; p < 2; p++) {
            int c = tid + p * 256;
            int row = c >> 3, kc = (c & 7) * 8;
            int nn = n0 + row;
            const float* s = W + ((size_t)(nn & 3) * V + (nn >> 2)) * V + k0 + kc;
            rb[p] = pack8(*(const float4*)s, *(const float4*)(s + 4));
            if constexpr (WRITEB)
                *(uint4*)(g_whh16 + (size_t)nn * V + k0 + kc) = rb[p];
        }
        if (tid < 128)
            ra = *(const uint4*)(hin + (size_t)(tid >> 3) * V + k0 + (tid & 7) * 8);
    };
    auto store = [&](int buf) {
#pragma unroll
        for (int p = 0; p < 2; p++) {
            int c = tid + p * 256;
            int row = c >> 3, kc = (c & 7) * 8;
            *(uint4*)(&sm.st.B[buf][row][kc]) = rb[p];
        }
        if (tid < 128)
            *(uint4*)(&sm.st.A[buf][tid >> 3][(tid & 7) * 8]) = ra;
    };

    load(0);
    store(0);
    load(BK);
    __syncthreads();

    for (int i = 0; i < niter; i++) {
        int p = i & 1;
        if (i + 1 < niter) store(p ^ 1);
        if (i + 2 < niter) load((i + 2) * BK);
        if (w < 4 && (i & 3) == w) {
#pragma unroll
            for (int kk = 0; kk < BK; kk += 16) {
                wmma::fragment<wmma::matrix_a, 16, 16, 16, __half, wmma::row_major> af;
                wmma::load_matrix_sync(af, &sm.st.A[p][0][kk], LDS);
#pragma unroll
                for (int nf = 0; nf < 4; nf++) {
                    wmma::fragment<wmma::matrix_b, 16, 16, 16, __half, wmma::col_major> bf;
                    wmma::load_matrix_sync(bf, &sm.st.B[p][nf * 16][kk], LDS);
                    wmma::mma_sync(acc[nf], af, bf, acc[nf]);
                }
            }
        }
        __syncthreads();
    }

    if (w < 4)
#pragma unroll
        for (int nf = 0; nf < 4; nf++)
            wmma::store_matrix_sync(&sm.ep.R[w][0][nf * 16], acc[nf], 68,
                                    wmma::mem_row_major);
    __syncthreads();
    for (int c = tid; c < 16 * 64; c += 256) {
        int m = c >> 6, n = c & 63;
        sm.ep.F[m][n] = sm.ep.R[0][m][n] + sm.ep.R[1][m][n]
                      + sm.ep.R[2][m][n] + sm.ep.R[3][m][n];
    }
    __syncthreads();
    if constexpr (DEC) dec_epilogue(sm.ep.F, blockIdx.x * 16, xrev);
    else               enc_epilogue(sm.ep.F, blockIdx.x * 16, t, hout);
}

// =====================================================================
// Encoder step t=0 (h0=c0=0): gates straight from interleaved xg + bias.
// Writes h0 into ping-pong buffer 0.
// =====================================================================
__global__ void step0_kernel()
{
    int idx = blockIdx.x * 256 + threadIdx.x;   // 16*V exactly
    int b = idx / V, j = idx - b * V;
    float4 x4 = *(const float4*)&g_xg[(size_t)(b * 8) * G4 + (size_t)j * 4];
    float4 bb = *(const float4*)&g_bep[j * 4];
    float i_ = sigf (x4.x + bb.x);
    float gg = tanhf(x4.z + bb.z);
    float o_ = sigf (x4.w + bb.w);
    float c  = i_ * gg;
    g_c[idx] = c;
    float h  = o_ * tanhf(c);
    g_h[idx]      = h;
    g_h16[0][idx] = __float2half(h);
}

// =====================================================================
__global__ void fc_enc_kernel(const float* __restrict__ wgt,
                              const float* __restrict__ bias,
                              float* __restrict__ out)
{
    __shared__ float red[256];
    int b = blockIdx.x;
    const float* h = g_h + (size_t)b * V;
    float s = 0.0f;
    for (int k = threadIdx.x; k < V; k += 256) s = fmaf(h[k], wgt[k], s);
    red[threadIdx.x] = s;
    __syncthreads();
    for (int st = 128; st > 0; st >>= 1) {
        if (threadIdx.x < st) red[threadIdx.x] += red[threadIdx.x + st];
        __syncthreads();
    }
    if (threadIdx.x == 0) out[b] = red[0] + bias[0];
}

// =====================================================================
__global__ void dec_out_kernel(const float* __restrict__ fcb,
                               float* __restrict__ out)
{
    int idx = blockIdx.x * 256 + threadIdx.x;   // 64*V exactly
    int m = idx / V, n = idx - m * V;
    float val = g_dec[idx] + fcb[n];
    int b = m >> 2, tr = m & 3;
    size_t base = 16 + (size_t)(b * 12 + tr * 3) * V + n;
    out[base]         = val;
    out[base + V]     = val;
    out[base + 2 * V] = val;
}

// =====================================================================
extern "C" void kernel_launch(void* const* d_in, const int* in_sizes, int n_in,
                              void* d_out, int out_size)
{
    (void)in_sizes; (void)n_in; (void)out_size;
    const float* x        = (const float*)d_in[0];
    const float* x_rev    = (const float*)d_in[1];
    const float* W_ih_enc = (const float*)d_in[2];
    const float* W_hh_enc = (const float*)d_in[3];
    const float* b_enc    = (const float*)d_in[4];
    const float* fc_enc_w = (const float*)d_in[5];
    const float* fc_enc_b = (const float*)d_in[6];
    const float* W_ih_dec = (const float*)d_in[7];
    const float* W_hh_dec = (const float*)d_in[8];
    const float* b_dec    = (const float*)d_in[9];
    const float* fc_dec_w = (const float*)d_in[10];
    const float* fc_dec_b = (const float*)d_in[11];
    float* out = (float*)d_out;

    __half *x16_p, *hd16_p;
    float  *xg_p, *dec_p;
    cudaGetSymbolAddress((void**)&x16_p,  g_x16);
    cudaGetSymbolAddress((void**)&hd16_p, g_hd16);
    cudaGetSymbolAddress((void**)&xg_p,   g_xg);
    cudaGetSymbolAddress((void**)&dec_p,  g_dec);

    // 0) x -> fp16; zero xg; permuted bias/W_ih_dec vectors
    conv16_kernel<<<(128 * V / 8 + 255) / 256, 256>>>(x, x16_p, 128 * V / 8);
    zero_kernel<<<(128 * G4 / 4 + 255) / 256, 256>>>(xg_p, 128 * G4 / 4);
    prep_kernel<<<(G4 + 255) / 256, 256>>>(b_enc, b_dec, W_ih_dec);

    // 1) xg += x @ W_ih_enc^T  (gate-interleaved cols, ksplit 2, mblocks 2)
    gemm16<64, 32, true><<<dim3(G4 / 128, 2, 2), 256>>>(
        x16_p, W_ih_enc, xg_p, G4, V / 2);

    // 2) encoder step 0 -> h buf 0
    step0_kernel<<<BSZ * V / 256, 256>>>();

    // 3) step 1: fused GEMM+gates; reads buf0, writes buf1; persists fp16 W
    rec_f32_kernel<true, false><<<G4 / 64, 256>>>(W_hh_enc, 1, nullptr);

    // 4) steps 2..7: fully fused cp.async recurrence (ping-pong h buffers)
    for (int t = 2; t < TT; t++)
        rec_ca_kernel<<<G4 / 64, 256>>>(t);

    // 5) enc_out -> d_out[0..15]
    fc_enc_kernel<<<BSZ, 256>>>(fc_enc_w, fc_enc_b, out);

    // 6) decoder: fused GEMM + all-TR gate epilogue (reads h buf1; zeroes g_dec)
    rec_f32_kernel<false, true><<<G4 / 64, 256>>>(W_hh_dec, 0, x_rev);

    // 7) dec += h_d @ fc_dec_w^T (ksplit 4), then bias + repeat(3) scatter
    gemm16<64, 32, false><<<dim3(V / 128, 4, 1), 256>>>(
        hd16_p, fc_dec_w, dec_p, V, V / 4);
    dec_out_kernel<<<BSZ * TR * V / 256, 256>>>(fc_dec_b, out);
}

// round 9
// speedup vs baseline: 1.0671x; 1.0671x over previous
#include <cuda_runtime.h>
#include <cuda_fp16.h>
#include <mma.h>
#include <cstddef>
#include <cstdint>

using namespace nvcuda;

#define V    6912
#define G4   27648   // 4*V
#define BSZ  16
#define TT   8
#define TR   4

// ---------------- device scratch (no allocation allowed) ----------------
// Gate-interleaved layouts: column/row index n' = j*4 + g  (g: 0=i,1=f,2=g,3=o)
__device__ __half g_whh16[(size_t)G4 * V];   // fp16 W_hh_enc, rows interleaved
__device__ __half g_x16 [128 * V];           // x fp16
__device__ __half g_h16 [2][BSZ * V];        // encoder h fp16, ping-pong
__device__ __half g_hd16[BSZ * TR * V];      // decoder h_d (fp16, GEMM A)
__device__ float  g_h   [BSZ * V];           // encoder h fp32 (fc_enc)
__device__ float  g_c   [BSZ * V];
__device__ float  g_xg  [128 * G4];          // xg, cols interleaved (plain store)
__device__ float  g_dec [BSZ * TR * V];      // fc_dec accumulator (atomic)
__device__ float  g_bep [G4];                // b_enc permuted
__device__ float  g_bdp [G4];                // b_dec permuted
__device__ float  g_widp[G4];                // W_ih_dec permuted

__device__ __forceinline__ float sigf(float x) { return 1.0f / (1.0f + expf(-x)); }

__device__ __forceinline__ uint4 pack8(float4 a, float4 b)
{
    __half2 h0 = __floats2half2_rn(a.x, a.y);
    __half2 h1 = __floats2half2_rn(a.z, a.w);
    __half2 h2 = __floats2half2_rn(b.x, b.y);
    __half2 h3 = __floats2half2_rn(b.z, b.w);
    uint4 u;
    u.x = *reinterpret_cast<unsigned*>(&h0);
    u.y = *reinterpret_cast<unsigned*>(&h1);
    u.z = *reinterpret_cast<unsigned*>(&h2);
    u.w = *reinterpret_cast<unsigned*>(&h3);
    return u;
}

// =====================================================================
__global__ void conv16_kernel(const float* __restrict__ src,
                              __half* __restrict__ dst, int n8)
{
    int idx = blockIdx.x * 256 + threadIdx.x;
    if (idx >= n8) return;
    const float4* s = (const float4*)src + (size_t)idx * 2;
    ((uint4*)dst)[idx] = pack8(s[0], s[1]);
}

// permute gate vectors: out[j*4+g] = in[g*V+j]
__global__ void prep_kernel(const float* __restrict__ be,
                            const float* __restrict__ bd,
                            const float* __restrict__ wid)
{
    int idx = blockIdx.x * 256 + threadIdx.x;
    if (idx >= G4) return;
    int src = (idx & 3) * V + (idx >> 2);
    g_bep[idx]  = be[src];
    g_bdp[idx]  = bd[src];
    g_widp[idx] = wid[src];
}

// =====================================================================
// Register-staged fp16-MMA GEMM.  C[m0+m][n] (+)= sum_k A[m0+m][k]*B[n][k]
//   PERM: B fp32 row n read from row (n&3)*V + (n>>2) (gate interleave)
//   ATOMIC: smem-collect + atomicAdd (K-split); else direct wmma store.
// =====================================================================
template<int BM, int BK, bool PERM, bool ATOMIC>
__global__ __launch_bounds__(256)
void gemm16(const __half* __restrict__ A, const float* __restrict__ Bf,
            float* __restrict__ C, int N, int klen)
{
    constexpr int BNB = 128, LDS = BK + 8;
    __shared__ __align__(16) __half sA[2][BM][LDS];
    __shared__ __align__(16) __half sB[2][BNB][LDS];
    __shared__ __align__(16) float  sC[ATOMIC ? BM : 1][BNB + 4];

    const int tid   = threadIdx.x;
    const int n0    = blockIdx.x * BNB;
    const int kbase = blockIdx.y * klen;
    const int m0    = blockIdx.z * BM;
    const int niter = klen / BK;

    constexpr int WARPS_M = (BM <= 16) ? 1 : 2;
    constexpr int WARPS_N = 8 / WARPS_M;
    constexpr int WM = BM / WARPS_M, WN = BNB / WARPS_N;
    constexpr int MF = WM / 16, NF = WN / 16;
    const int w  = tid >> 5;
    const int wm = w / WARPS_N, wn = w % WARPS_N;

    wmma::fragment<wmma::accumulator, 16, 16, 16, float> acc[MF][NF];
#pragma unroll
    for (int i = 0; i < MF; i++)
#pragma unroll
        for (int j = 0; j < NF; j++) wmma::fill_fragment(acc[i][j], 0.0f);

    constexpr int CPR   = BK / 8;
    constexpr int BCH   = BNB * CPR / 256;
    constexpr int ACH_T = BM * CPR;
    constexpr int ACH   = (ACH_T + 255) / 256;

    uint4 rb[BCH], ra[ACH];

    auto load = [&](int k0) {
#pragma unroll
        for (int p = 0; p < BCH; p++) {
            int c = tid + p * 256;
            int row = c / CPR, kc = (c % CPR) * 8;
            int nn = n0 + row;
            size_t srow = PERM ? ((size_t)(nn & 3) * V + (nn >> 2)) : (size_t)nn;
            const float* s = Bf + srow * V + k0 + kc;
            rb[p] = pack8(*(const float4*)s, *(const float4*)(s + 4));
        }
#pragma unroll
        for (int p = 0; p < ACH; p++) {
            int c = tid + p * 256;
            if (ACH_T >= (p + 1) * 256 || c < ACH_T) {
                int row = c / CPR, kc = (c % CPR) * 8;
                ra[p] = *(const uint4*)(A + (size_t)(m0 + row) * V + k0 + kc);
            }
        }
    };
    auto store = [&](int buf) {
#pragma unroll
        for (int p = 0; p < BCH; p++) {
            int c = tid + p * 256;
            int row = c / CPR, kc = (c % CPR) * 8;
            *(uint4*)(&sB[buf][row][kc]) = rb[p];
        }
#pragma unroll
        for (int p = 0; p < ACH; p++) {
            int c = tid + p * 256;
            if (ACH_T >= (p + 1) * 256 || c < ACH_T) {
                int row = c / CPR, kc = (c % CPR) * 8;
                *(uint4*)(&sA[buf][row][kc]) = ra[p];
            }
        }
    };

    load(kbase);
    store(0);
    if (niter > 1) load(kbase + BK);
    __syncthreads();

    for (int i = 0; i < niter; i++) {
        int p = i & 1;
        if (i + 1 < niter) store(p ^ 1);
        if (i + 2 < niter) load(kbase + (i + 2) * BK);
#pragma unroll
        for (int kk = 0; kk < BK; kk += 16) {
            wmma::fragment<wmma::matrix_a, 16, 16, 16, __half, wmma::row_major> af[MF];
            wmma::fragment<wmma::matrix_b, 16, 16, 16, __half, wmma::col_major> bf[NF];
#pragma unroll
            for (int i_ = 0; i_ < MF; i_++)
                wmma::load_matrix_sync(af[i_], &sA[p][wm * WM + i_ * 16][kk], LDS);
#pragma unroll
            for (int j_ = 0; j_ < NF; j_++)
                wmma::load_matrix_sync(bf[j_], &sB[p][wn * WN + j_ * 16][kk], LDS);
#pragma unroll
            for (int i_ = 0; i_ < MF; i_++)
#pragma unroll
                for (int j_ = 0; j_ < NF; j_++)
                    wmma::mma_sync(acc[i_][j_], af[i_], bf[j_], acc[i_][j_]);
        }
        __syncthreads();
    }

    if constexpr (ATOMIC) {
#pragma unroll
        for (int i_ = 0; i_ < MF; i_++)
#pragma unroll
            for (int j_ = 0; j_ < NF; j_++)
                wmma::store_matrix_sync(&sC[wm * WM + i_ * 16][wn * WN + j_ * 16],
                                        acc[i_][j_], BNB + 4, wmma::mem_row_major);
        __syncthreads();
        for (int c = tid; c < BM * BNB; c += 256) {
            int m = c / BNB, n = c - m * BNB;
            atomicAdd(&C[(size_t)(m0 + m) * N + n0 + n], sC[m][n]);
        }
    } else {
#pragma unroll
        for (int i_ = 0; i_ < MF; i_++)
#pragma unroll
            for (int j_ = 0; j_ < NF; j_++)
                wmma::store_matrix_sync(
                    C + (size_t)(m0 + wm * WM + i_ * 16) * N + n0 + wn * WN + j_ * 16,
                    acc[i_][j_], N, wmma::mem_row_major);
    }
}

// =====================================================================
// Fused LSTM-step epilogues (block owns 16 complete units j, all gates).
// =====================================================================
__device__ __forceinline__ void enc_epilogue(float (*sF)[64], int jbase, int t,
                                             __half* __restrict__ hout)
{
    int tid = threadIdx.x;
    int b = tid >> 4, jl = tid & 15;
    int jg = jbase + jl;
    float4 pre = *(float4*)&sF[b][jl * 4];
    float4 xg4 = *(const float4*)&g_xg[(size_t)(b * 8 + t) * G4 + (size_t)jg * 4];
    float4 bb  = *(const float4*)&g_bep[jg * 4];
    float i_ = sigf (pre.x + xg4.x + bb.x);
    float f_ = sigf (pre.y + xg4.y + bb.y);
    float gg = tanhf(pre.z + xg4.z + bb.z);
    float o_ = sigf (pre.w + xg4.w + bb.w);
    int idx = b * V + jg;
    float c = f_ * g_c[idx] + i_ * gg;
    g_c[idx] = c;
    float h = o_ * tanhf(c);
    g_h[idx]  = h;
    hout[idx] = __float2half(h);
}

__device__ __forceinline__ void dec_epilogue(float (*sF)[64], int jbase,
                                             const float* __restrict__ xrev)
{
    int tid = threadIdx.x;
    int b = tid >> 4, jl = tid & 15;
    int jg = jbase + jl;
    float4 pre = *(float4*)&sF[b][jl * 4];
    float4 bb  = *(const float4*)&g_bdp[jg * 4];
    float4 ww  = *(const float4*)&g_widp[jg * 4];
    float bi = pre.x + bb.x, bf = pre.y + bb.y;
    float bg = pre.z + bb.z, bo = pre.w + bb.w;
    float ce = g_c[b * V + jg];
#pragma unroll
    for (int tr = 0; tr < TR; tr++) {
        float xr = xrev[b * TR + tr];
        float i_ = sigf (bi + xr * ww.x);
        float f_ = sigf (bf + xr * ww.y);
        float gg = tanhf(bg + xr * ww.z);
        float o_ = sigf (bo + xr * ww.w);
        float cd = f_ * ce + i_ * gg;
        size_t o = (size_t)(b * TR + tr) * V + jg;
        g_hd16[o] = __float2half(o_ * tanhf(cd));
        g_dec[o]  = 0.f;                 // pre-zero for fc_dec atomics
    }
}

// Shared epilogue combine: 8 warp partials (fragment f = w&3, k-half = w>>2)
// sR[8][16][32] -> sF[16][64]
__device__ __forceinline__ void combine8(float (*sR)[16][32], float (*sF)[64])
{
    int tid = threadIdx.x;
    for (int c = tid; c < 16 * 64; c += 256) {
        int m = c >> 6, n = c & 63;
        int f = n >> 4, cc = n & 15;
        sF[m][n] = sR[f][m][cc] + sR[f + 4][m][cc];
    }
}

// =====================================================================
// Fused recurrence step, fp16 interleaved weights (steps 2..7).
// Reads g_h16[(t+1)&1], writes g_h16[t&1].  8-warp compute spread:
// warp w computes fragment (w&3) on iterations with parity (w>>2).
// =====================================================================
__global__ __launch_bounds__(256) void rec_ca_kernel(int t)
{
    constexpr int BK = 64, STAGES = 4, BNN = 64, LDS = BK + 8;
    union SM {
        struct { __half A[STAGES][16][LDS]; __half B[STAGES][BNN][LDS]; } st;
        struct { float R[8][16][32]; float F[16][64]; } ep;
    };
    __shared__ __align__(16) SM sm;

    const __half* hin  = g_h16[(t + 1) & 1];
    __half*       hout = g_h16[t & 1];

    const int tid = threadIdx.x;
    const int w   = tid >> 5;
    const int nf  = w & 3;
    const int kh  = w >> 2;
    const int n0  = blockIdx.x * BNN;
    const int niter = V / BK;   // 108

    wmma::fragment<wmma::accumulator, 16, 16, 16, float> acc;
    wmma::fill_fragment(acc, 0.0f);

    auto stage = [&](int s, int k0) {
#pragma unroll
        for (int p = 0; p < 2; p++) {
            int c = tid + p * 256;
            int row = c >> 3, kc = (c & 7) * 8;
            uint32_t d = (uint32_t)__cvta_generic_to_shared(&sm.st.B[s][row][kc]);
            const void* g = g_whh16 + (size_t)(n0 + row) * V + k0 + kc;
            asm volatile("cp.async.cg.shared.global [%0], [%1], 16;\n" :: "r"(d), "l"(g));
        }
        if (tid < 128) {
            int row = tid >> 3, kc = (tid & 7) * 8;
            uint32_t d = (uint32_t)__cvta_generic_to_shared(&sm.st.A[s][row][kc]);
            const void* g = hin + (size_t)row * V + k0 + kc;
            asm volatile("cp.async.cg.shared.global [%0], [%1], 16;\n" :: "r"(d), "l"(g));
        }
        asm volatile("cp.async.commit_group;\n");
    };

    int issued = 0;
    for (; issued < STAGES - 1; issued++) stage(issued, issued * BK);

    for (int i = 0; i < niter; i++) {
        if (issued < niter) { stage(issued % STAGES, issued * BK); issued++; }
        else                { asm volatile("cp.async.commit_group;\n"); }
        asm volatile("cp.async.wait_group %0;\n" :: "n"(STAGES - 1));
        __syncthreads();
        int s = i % STAGES;
        if ((i & 1) == kh) {
#pragma unroll
            for (int kk = 0; kk < BK; kk += 16) {
                wmma::fragment<wmma::matrix_a, 16, 16, 16, __half, wmma::row_major> af;
                wmma::fragment<wmma::matrix_b, 16, 16, 16, __half, wmma::col_major> bf;
                wmma::load_matrix_sync(af, &sm.st.A[s][0][kk], LDS);
                wmma::load_matrix_sync(bf, &sm.st.B[s][nf * 16][kk], LDS);
                wmma::mma_sync(acc, af, bf, acc);
            }
        }
        __syncthreads();
    }

    wmma::store_matrix_sync(&sm.ep.R[w][0][0], acc, 32, wmma::mem_row_major);
    __syncthreads();
    combine8(sm.ep.R, sm.ep.F);
    __syncthreads();
    enc_epilogue(sm.ep.F, blockIdx.x * 16, t, hout);
}

// =====================================================================
// Fused recurrence/decoder step, fp32 weights read with gate-interleave
// permutation + in-register fp16 convert.  WRITEB: persist fp16 copy.
// =====================================================================
template<bool WRITEB, bool DEC>
__global__ __launch_bounds__(256) void rec_f32_kernel(
    const float* __restrict__ W, int t, const float* __restrict__ xrev)
{
    constexpr int BK = 64, BNN = 64, LDS = BK + 8;
    union SM {
        struct { __half A[2][16][LDS]; __half B[2][BNN][LDS]; } st;
        struct { float R[8][16][32]; float F[16][64]; } ep;
    };
    __shared__ __align__(16) SM sm;

    const __half* hin  = g_h16[(t + 1) & 1];
    __half*       hout = g_h16[t & 1];

    const int tid = threadIdx.x;
    const int w   = tid >> 5;
    const int nf  = w & 3;
    const int kh  = w >> 2;
    const int n0  = blockIdx.x * BNN;
    const int niter = V / BK;   // 108

    wmma::fragment<wmma::accumulator, 16, 16, 16, float> acc;
    wmma::fill_fragment(acc, 0.0f);

    uint4 rb[2], ra;

    auto load = [&](int k0) {
#pragma unroll
        for (int p = 0; p < 2; p++) {
            int c = tid + p * 256;
            int row = c >> 3, kc = (c & 7) * 8;
            int nn = n0 + row;
            const float* s = W + ((size_t)(nn & 3) * V + (nn >> 2)) * V + k0 + kc;
            rb[p] = pack8(*(const float4*)s, *(const float4*)(s + 4));
            if constexpr (WRITEB)
                *(uint4*)(g_whh16 + (size_t)nn * V + k0 + kc) = rb[p];
        }
        if (tid < 128)
            ra = *(const uint4*)(hin + (size_t)(tid >> 3) * V + k0 + (tid & 7) * 8);
    };
    auto store = [&](int buf) {
#pragma unroll
        for (int p = 0; p < 2; p++) {
            int c = tid + p * 256;
            int row = c >> 3, kc = (c & 7) * 8;
            *(uint4*)(&sm.st.B[buf][row][kc]) = rb[p];
        }
        if (tid < 128)
            *(uint4*)(&sm.st.A[buf][tid >> 3][(tid & 7) * 8]) = ra;
    };

    load(0);
    store(0);
    load(BK);
    __syncthreads();

    for (int i = 0; i < niter; i++) {
        int p = i & 1;
        if (i + 1 < niter) store(p ^ 1);
        if (i + 2 < niter) load((i + 2) * BK);
        if ((i & 1) == kh) {
#pragma unroll
            for (int kk = 0; kk < BK; kk += 16) {
                wmma::fragment<wmma::matrix_a, 16, 16, 16, __half, wmma::row_major> af;
                wmma::fragment<wmma::matrix_b, 16, 16, 16, __half, wmma::col_major> bf;
                wmma::load_matrix_sync(af, &sm.st.A[p][0][kk], LDS);
                wmma::load_matrix_sync(bf, &sm.st.B[p][nf * 16][kk], LDS);
                wmma::mma_sync(acc, af, bf, acc);
            }
        }
        __syncthreads();
    }

    wmma::store_matrix_sync(&sm.ep.R[w][0][0], acc, 32, wmma::mem_row_major);
    __syncthreads();
    combine8(sm.ep.R, sm.ep.F);
    __syncthreads();
    if constexpr (DEC) dec_epilogue(sm.ep.F, blockIdx.x * 16, xrev);
    else               enc_epilogue(sm.ep.F, blockIdx.x * 16, t, hout);
}

// =====================================================================
// Encoder step t=0 (h0=c0=0): gates straight from interleaved xg + bias.
// =====================================================================
__global__ void step0_kernel()
{
    int idx = blockIdx.x * 256 + threadIdx.x;   // 16*V exactly
    int b = idx / V, j = idx - b * V;
    float4 x4 = *(const float4*)&g_xg[(size_t)(b * 8) * G4 + (size_t)j * 4];
    float4 bb = *(const float4*)&g_bep[j * 4];
    float i_ = sigf (x4.x + bb.x);
    float gg = tanhf(x4.z + bb.z);
    float o_ = sigf (x4.w + bb.w);
    float c  = i_ * gg;
    g_c[idx] = c;
    float h  = o_ * tanhf(c);
    g_h[idx]      = h;
    g_h16[0][idx] = __float2half(h);
}

// =====================================================================
__global__ void fc_enc_kernel(const float* __restrict__ wgt,
                              const float* __restrict__ bias,
                              float* __restrict__ out)
{
    __shared__ float red[256];
    int b = blockIdx.x;
    const float* h = g_h + (size_t)b * V;
    float s = 0.0f;
    for (int k = threadIdx.x; k < V; k += 256) s = fmaf(h[k], wgt[k], s);
    red[threadIdx.x] = s;
    __syncthreads();
    for (int st = 128; st > 0; st >>= 1) {
        if (threadIdx.x < st) red[threadIdx.x] += red[threadIdx.x + st];
        __syncthreads();
    }
    if (threadIdx.x == 0) out[b] = red[0] + bias[0];
}

// =====================================================================
__global__ void dec_out_kernel(const float* __restrict__ fcb,
                               float* __restrict__ out)
{
    int idx = blockIdx.x * 256 + threadIdx.x;   // 64*V exactly
    int m = idx / V, n = idx - m * V;
    float val = g_dec[idx] + fcb[n];
    int b = m >> 2, tr = m & 3;
    size_t base = 16 + (size_t)(b * 12 + tr * 3) * V + n;
    out[base]         = val;
    out[base + V]     = val;
    out[base + 2 * V] = val;
}

// =====================================================================
extern "C" void kernel_launch(void* const* d_in, const int* in_sizes, int n_in,
                              void* d_out, int out_size)
{
    (void)in_sizes; (void)n_in; (void)out_size;
    const float* x        = (const float*)d_in[0];
    const float* x_rev    = (const float*)d_in[1];
    const float* W_ih_enc = (const float*)d_in[2];
    const float* W_hh_enc = (const float*)d_in[3];
    const float* b_enc    = (const float*)d_in[4];
    const float* fc_enc_w = (const float*)d_in[5];
    const float* fc_enc_b = (const float*)d_in[6];
    const float* W_ih_dec = (const float*)d_in[7];
    const float* W_hh_dec = (const float*)d_in[8];
    const float* b_dec    = (const float*)d_in[9];
    const float* fc_dec_w = (const float*)d_in[10];
    const float* fc_dec_b = (const float*)d_in[11];
    float* out = (float*)d_out;

    __half *x16_p, *hd16_p;
    float  *xg_p, *dec_p;
    cudaGetSymbolAddress((void**)&x16_p,  g_x16);
    cudaGetSymbolAddress((void**)&hd16_p, g_hd16);
    cudaGetSymbolAddress((void**)&xg_p,   g_xg);
    cudaGetSymbolAddress((void**)&dec_p,  g_dec);

    // 0) x -> fp16; permuted bias/W_ih_dec vectors
    conv16_kernel<<<(128 * V / 8 + 255) / 256, 256>>>(x, x16_p, 128 * V / 8);
    prep_kernel<<<(G4 + 255) / 256, 256>>>(b_enc, b_dec, W_ih_dec);

    // 1) xg = x @ W_ih_enc^T  (full-K, direct store, 2 m-blocks, 432 blocks)
    gemm16<64, 32, true, false><<<dim3(G4 / 128, 1, 2), 256>>>(
        x16_p, W_ih_enc, xg_p, G4, V);

    // 2) encoder step 0 -> h buf 0
    step0_kernel<<<BSZ * V / 256, 256>>>();

    // 3) step 1: fused GEMM+gates; reads buf0, writes buf1; persists fp16 W
    rec_f32_kernel<true, false><<<G4 / 64, 256>>>(W_hh_enc, 1, nullptr);

    // 4) steps 2..7: fully fused cp.async recurrence (ping-pong h buffers)
    for (int t = 2; t < TT; t++)
        rec_ca_kernel<<<G4 / 64, 256>>>(t);

    // 5) enc_out -> d_out[0..15]
    fc_enc_kernel<<<BSZ, 256>>>(fc_enc_w, fc_enc_b, out);

    // 6) decoder: fused GEMM + all-TR gate epilogue (reads buf1; zeroes g_dec)
    rec_f32_kernel<false, true><<<G4 / 64, 256>>>(W_hh_dec, 0, x_rev);

    // 7) dec += h_d @ fc_dec_w^T (ksplit 4, atomic), bias + repeat(3) scatter
    gemm16<64, 32, false, true><<<dim3(V / 128, 4, 1), 256>>>(
        hd16_p, fc_dec_w, dec_p, V, V / 4);
    dec_out_kernel<<<BSZ * TR * V / 256, 256>>>(fc_dec_b, out);
}